// round 2
// baseline (speedup 1.0000x reference)
#include <cuda_runtime.h>
#include <math.h>

// Problem constants (fixed by reference setup_inputs)
#define BATCH 8
#define LQ    10000
#define CDIM  256
#define NHEAD 8
#define NPNT  4
#define DFFN  1024
#define HIMG  100
#define WIMG  100
#define HDIM  32                 // CDIM / NHEAD
#define MROWS (BATCH * LQ)       // 80000

// ---------------------------------------------------------------------------
// Scratch (device globals; no cudaMalloc allowed)
// ---------------------------------------------------------------------------
__device__ float g_value [(size_t)MROWS * CDIM];                 // 80 MB
__device__ float g_off   [(size_t)MROWS * NHEAD * NPNT * 2];     // 20 MB
__device__ float g_aw    [(size_t)MROWS * NHEAD * NPNT];         // 10 MB
__device__ float g_attn  [(size_t)MROWS * CDIM];                 // 80 MB
__device__ float g_tmp   [(size_t)MROWS * CDIM];                 // 80 MB
__device__ float g_q     [(size_t)MROWS * CDIM];                 // 80 MB
__device__ float g_hidden[(size_t)MROWS * DFFN];                 // 327 MB

// ---------------------------------------------------------------------------
// Packed f32x2 helpers (Blackwell FFMA2 pipe; PTX-only, bit-exact fp32)
// ---------------------------------------------------------------------------
__device__ __forceinline__ unsigned long long pk2(float lo, float hi) {
    unsigned long long r;
    asm("mov.b64 %0, {%1, %2};" : "=l"(r) : "f"(lo), "f"(hi));
    return r;
}
__device__ __forceinline__ void ffma2(unsigned long long& d,
                                      unsigned long long a,
                                      unsigned long long b) {
    asm("fma.rn.f32x2 %0, %1, %2, %3;" : "=l"(d) : "l"(a), "l"(b), "l"(d));
}
__device__ __forceinline__ float2 upk2(unsigned long long v) {
    float lo, hi;
    asm("mov.b64 {%0, %1}, %2;" : "=f"(lo), "=f"(hi) : "l"(v));
    return make_float2(lo, hi);
}

// ---------------------------------------------------------------------------
// Big fp32 GEMM with packed f32x2 FMA:
//   C[M,N] = A[M,K] @ W[K,N] + bias (+relu | +residual)
// Tile 128x128, BK=16, 256 threads, 8x8 micro-tile per thread.
// Requires: M % 128 == 0 (80000 = 625*128), N % 128 == 0, K % 16 == 0.
// EPI: 0 = bias, 1 = bias+relu, 2 = bias+residual
// ---------------------------------------------------------------------------
template<int EPI>
__global__ void __launch_bounds__(256) gemm128_kernel(
    const float* __restrict__ A, const float* __restrict__ W,
    const float* __restrict__ bias, const float* __restrict__ resid,
    float* __restrict__ C, int N, int K)
{
    __shared__ float As[16][128];   // [k][m]
    __shared__ float Bs[16][128];   // [k][n]

    const int tid = threadIdx.x;
    const int bm  = blockIdx.y * 128;
    const int bn  = blockIdx.x * 128;
    const int tx  = tid & 15;        // micro-tile col group (8 cols)
    const int ty  = tid >> 4;        // micro-tile row group (8 rows)

    // A-load mapping: 2 float4 per thread
    const int a_row = tid >> 1;              // 0..127
    const int a_k   = (tid & 1) * 8;         // 0 or 8
    // B-load mapping: 2 float4 per thread
    const int b_k   = tid >> 4;              // 0..15
    const int b_n   = (tid & 15) * 8;        // 0..120

    unsigned long long acc[8][4];
    #pragma unroll
    for (int i = 0; i < 8; i++)
        #pragma unroll
        for (int j = 0; j < 4; j++) acc[i][j] = 0ull;

    for (int k0 = 0; k0 < K; k0 += 16) {
        float4 av0 = *(const float4*)&A[(size_t)(bm + a_row) * K + k0 + a_k];
        float4 av1 = *(const float4*)&A[(size_t)(bm + a_row) * K + k0 + a_k + 4];
        float4 bv0 = *(const float4*)&W[(size_t)(k0 + b_k) * N + bn + b_n];
        float4 bv1 = *(const float4*)&W[(size_t)(k0 + b_k) * N + bn + b_n + 4];

        As[a_k + 0][a_row] = av0.x;
        As[a_k + 1][a_row] = av0.y;
        As[a_k + 2][a_row] = av0.z;
        As[a_k + 3][a_row] = av0.w;
        As[a_k + 4][a_row] = av1.x;
        As[a_k + 5][a_row] = av1.y;
        As[a_k + 6][a_row] = av1.z;
        As[a_k + 7][a_row] = av1.w;
        *(float4*)&Bs[b_k][b_n]     = bv0;
        *(float4*)&Bs[b_k][b_n + 4] = bv1;
        __syncthreads();

        #pragma unroll
        for (int k = 0; k < 16; ++k) {
            float4 a0 = *(const float4*)&As[k][ty * 8];
            float4 a1 = *(const float4*)&As[k][ty * 8 + 4];
            // B pairs read directly as packed 64-bit (adjacent cols)
            ulonglong2 bp0 = *(const ulonglong2*)&Bs[k][tx * 8];
            ulonglong2 bp1 = *(const ulonglong2*)&Bs[k][tx * 8 + 4];
            unsigned long long bb[4] = {bp0.x, bp0.y, bp1.x, bp1.y};
            float ar[8] = {a0.x, a0.y, a0.z, a0.w, a1.x, a1.y, a1.z, a1.w};
            #pragma unroll
            for (int i = 0; i < 8; i++) {
                unsigned long long aa = pk2(ar[i], ar[i]);
                #pragma unroll
                for (int j = 0; j < 4; j++)
                    ffma2(acc[i][j], aa, bb[j]);
            }
        }
        __syncthreads();
    }

    #pragma unroll
    for (int i = 0; i < 8; i++) {
        const int row = bm + ty * 8 + i;
        float o[8];
        #pragma unroll
        for (int j = 0; j < 4; j++) {
            float2 v = upk2(acc[i][j]);
            o[2 * j]     = v.x;
            o[2 * j + 1] = v.y;
        }
        const int col = bn + tx * 8;
        #pragma unroll
        for (int j = 0; j < 8; j++) {
            float v = o[j] + bias[col + j];
            if (EPI == 1) v = fmaxf(v, 0.f);
            if (EPI == 2) v += resid[(size_t)row * N + col + j];
            o[j] = v;
        }
        *(float4*)&C[(size_t)row * N + col]     = make_float4(o[0], o[1], o[2], o[3]);
        *(float4*)&C[(size_t)row * N + col + 4] = make_float4(o[4], o[5], o[6], o[7]);
    }
}

// ---------------------------------------------------------------------------
// Small-N fp32 GEMM (N = 32 / 64): tile 64xN, BK=16, 256 threads, 4x4 micro.
// ---------------------------------------------------------------------------
__global__ void __launch_bounds__(256) gemm_small_kernel(
    const float* __restrict__ A, const float* __restrict__ W,
    const float* __restrict__ bias, float* __restrict__ C, int N, int K)
{
    __shared__ float As[16][64];
    __shared__ float Bs[16][64];

    const int tid = threadIdx.x;
    const int bm  = blockIdx.y * 64;
    const int tx  = tid & 15;
    const int ty  = tid >> 4;
    const int a_row = tid >> 2;
    const int a_k4  = (tid & 3) << 2;
    const int b_k   = tid >> 4;
    const int b_n4  = (tid & 15) << 2;
    const bool bvalid = b_n4 < N;

    float acc[4][4];
    #pragma unroll
    for (int i = 0; i < 4; i++)
        #pragma unroll
        for (int j = 0; j < 4; j++) acc[i][j] = 0.f;

    for (int k0 = 0; k0 < K; k0 += 16) {
        float4 av = *(const float4*)&A[(size_t)(bm + a_row) * K + k0 + a_k4];
        float4 bv = make_float4(0.f, 0.f, 0.f, 0.f);
        if (bvalid)
            bv = *(const float4*)&W[(size_t)(k0 + b_k) * N + b_n4];

        As[a_k4 + 0][a_row] = av.x;
        As[a_k4 + 1][a_row] = av.y;
        As[a_k4 + 2][a_row] = av.z;
        As[a_k4 + 3][a_row] = av.w;
        *(float4*)&Bs[b_k][b_n4] = bv;
        __syncthreads();

        #pragma unroll
        for (int k = 0; k < 16; ++k) {
            float4 a4 = *(const float4*)&As[k][ty * 4];
            float4 b4 = *(const float4*)&Bs[k][tx * 4];
            float ar[4] = {a4.x, a4.y, a4.z, a4.w};
            float br[4] = {b4.x, b4.y, b4.z, b4.w};
            #pragma unroll
            for (int i = 0; i < 4; i++)
                #pragma unroll
                for (int j = 0; j < 4; j++)
                    acc[i][j] = fmaf(ar[i], br[j], acc[i][j]);
        }
        __syncthreads();
    }

    #pragma unroll
    for (int i = 0; i < 4; i++) {
        const int row = bm + ty * 4 + i;
        #pragma unroll
        for (int j = 0; j < 4; j++) {
            const int col = tx * 4 + j;
            if (col < N)
                C[(size_t)row * N + col] = acc[i][j] + bias[col];
        }
    }
}

// ---------------------------------------------------------------------------
// Deformable sampling: one warp per (b, q, h); lane = channel within head.
// ---------------------------------------------------------------------------
__global__ void sample_kernel(const float* __restrict__ refpts,
                              float* __restrict__ out)
{
    const int gtid = blockIdx.x * blockDim.x + threadIdx.x;
    const int warp = gtid >> 5;
    const int lane = gtid & 31;
    if (warp >= MROWS * NHEAD) return;

    const int h  = warp & (NHEAD - 1);
    const int bq = warp >> 3;
    const int b  = bq / LQ;

    const float rx = refpts[(size_t)bq * 2 + 0] * (float)WIMG;
    const float ry = refpts[(size_t)bq * 2 + 1] * (float)HIMG;

    // softmax over the 4 sampling-point logits
    const float* awp = &g_aw[(size_t)bq * (NHEAD * NPNT) + h * NPNT];
    float a0 = awp[0], a1 = awp[1], a2 = awp[2], a3 = awp[3];
    float m  = fmaxf(fmaxf(a0, a1), fmaxf(a2, a3));
    float e0 = __expf(a0 - m), e1 = __expf(a1 - m);
    float e2 = __expf(a2 - m), e3 = __expf(a3 - m);
    float inv = 1.f / (e0 + e1 + e2 + e3);
    float aws[4] = {e0 * inv, e1 * inv, e2 * inv, e3 * inv};

    const float* offp  = &g_off[(size_t)bq * (NHEAD * NPNT * 2) + h * NPNT * 2];
    const float* vbase = &g_value[(size_t)b * LQ * CDIM + h * HDIM + lane];

    float acc = 0.f;
    #pragma unroll
    for (int p = 0; p < NPNT; p++) {
        // x = ref.x*W + off.x - 0.5   (normalizer (W,H) == (100,100))
        float x = rx + offp[2 * p + 0] - 0.5f;
        float y = ry + offp[2 * p + 1] - 0.5f;
        float x0f = floorf(x), y0f = floorf(y);
        float lx = x - x0f, ly = y - y0f;
        int x0 = (int)x0f, y0 = (int)y0f;
        float w = aws[p];
        float wc[4] = {(1.f - lx) * (1.f - ly), lx * (1.f - ly),
                       (1.f - lx) * ly,         lx * ly};
        int xs[4] = {x0, x0 + 1, x0,     x0 + 1};
        int ys[4] = {y0, y0,     y0 + 1, y0 + 1};
        #pragma unroll
        for (int c = 0; c < 4; c++) {
            int xi = xs[c], yi = ys[c];
            if (xi >= 0 && xi < WIMG && yi >= 0 && yi < HIMG) {
                float v = vbase[(size_t)(yi * WIMG + xi) * CDIM];
                acc = fmaf(w * wc[c], v, acc);
            }
        }
    }
    out[(size_t)bq * CDIM + h * HDIM + lane] = acc;
}

// ---------------------------------------------------------------------------
// LayerNorm over C=256: one warp per row, 8 elements per lane (2x float4).
// ---------------------------------------------------------------------------
__global__ void ln_kernel(const float* __restrict__ x,
                          const float* __restrict__ g,
                          const float* __restrict__ be,
                          float* __restrict__ y)
{
    const int gtid = blockIdx.x * blockDim.x + threadIdx.x;
    const int row  = gtid >> 5;
    const int lane = gtid & 31;
    if (row >= MROWS) return;

    const float* xr = x + (size_t)row * CDIM;
    float4 v0 = *(const float4*)&xr[lane * 4];
    float4 v1 = *(const float4*)&xr[128 + lane * 4];

    float s  = v0.x + v0.y + v0.z + v0.w + v1.x + v1.y + v1.z + v1.w;
    float sq = v0.x * v0.x + v0.y * v0.y + v0.z * v0.z + v0.w * v0.w
             + v1.x * v1.x + v1.y * v1.y + v1.z * v1.z + v1.w * v1.w;
    #pragma unroll
    for (int o = 16; o; o >>= 1) {
        s  += __shfl_xor_sync(0xffffffffu, s,  o);
        sq += __shfl_xor_sync(0xffffffffu, sq, o);
    }
    const float mean = s * (1.f / CDIM);
    const float var  = sq * (1.f / CDIM) - mean * mean;
    const float istd = rsqrtf(var + 1e-5f);

    float* yr = y + (size_t)row * CDIM;
    const int c0 = lane * 4;
    float4 o0, o1;
    o0.x = (v0.x - mean) * istd * g[c0 + 0] + be[c0 + 0];
    o0.y = (v0.y - mean) * istd * g[c0 + 1] + be[c0 + 1];
    o0.z = (v0.z - mean) * istd * g[c0 + 2] + be[c0 + 2];
    o0.w = (v0.w - mean) * istd * g[c0 + 3] + be[c0 + 3];
    o1.x = (v1.x - mean) * istd * g[128 + c0 + 0] + be[128 + c0 + 0];
    o1.y = (v1.y - mean) * istd * g[128 + c0 + 1] + be[128 + c0 + 1];
    o1.z = (v1.z - mean) * istd * g[128 + c0 + 2] + be[128 + c0 + 2];
    o1.w = (v1.w - mean) * istd * g[128 + c0 + 3] + be[128 + c0 + 3];
    *(float4*)&yr[c0]       = o0;
    *(float4*)&yr[128 + c0] = o1;
}

// ---------------------------------------------------------------------------
// Launch sequence (graph-capturable: kernel launches only)
// ---------------------------------------------------------------------------
extern "C" void kernel_launch(void* const* d_in, const int* in_sizes, int n_in,
                              void* d_out, int out_size)
{
    const float* query = (const float*)d_in[0];
    const float* src   = (const float*)d_in[1];
    const float* refp  = (const float*)d_in[2];
    // d_in[3] spatial_shapes (int64), d_in[4] level_start_index (int64): fixed
    const float* W_off = (const float*)d_in[5];
    const float* b_off = (const float*)d_in[6];
    const float* W_aw  = (const float*)d_in[7];
    const float* b_aw  = (const float*)d_in[8];
    const float* W_val = (const float*)d_in[9];
    const float* b_val = (const float*)d_in[10];
    const float* W_out = (const float*)d_in[11];
    const float* b_out = (const float*)d_in[12];
    const float* g1    = (const float*)d_in[13];
    const float* be1   = (const float*)d_in[14];
    const float* W1    = (const float*)d_in[15];
    const float* b1    = (const float*)d_in[16];
    const float* W2    = (const float*)d_in[17];
    const float* b2    = (const float*)d_in[18];
    const float* g2    = (const float*)d_in[19];
    const float* be2   = (const float*)d_in[20];
    float* out = (float*)d_out;

    float *p_value, *p_off, *p_aw, *p_attn, *p_tmp, *p_q, *p_hidden;
    cudaGetSymbolAddress((void**)&p_value,  g_value);
    cudaGetSymbolAddress((void**)&p_off,    g_off);
    cudaGetSymbolAddress((void**)&p_aw,     g_aw);
    cudaGetSymbolAddress((void**)&p_attn,   g_attn);
    cudaGetSymbolAddress((void**)&p_tmp,    g_tmp);
    cudaGetSymbolAddress((void**)&p_q,      g_q);
    cudaGetSymbolAddress((void**)&p_hidden, g_hidden);

    const int MB128 = MROWS / 128;  // 625 row-tiles
    const int MB64  = MROWS / 64;   // 1250 row-tiles

    // 1) value = src @ W_val + b_val                       [80000 x 256 x 256]
    gemm128_kernel<0><<<dim3(256 / 128, MB128), 256>>>(src, W_val, b_val, nullptr, p_value, 256, 256);
    // 2) off logits = query @ W_off + b_off                [80000 x 64 x 256]
    gemm_small_kernel<<<dim3(1, MB64), 256>>>(query, W_off, b_off, p_off, 64, 256);
    // 3) aw logits = query @ W_aw + b_aw                   [80000 x 32 x 256]
    gemm_small_kernel<<<dim3(1, MB64), 256>>>(query, W_aw, b_aw, p_aw, 32, 256);
    // 4) softmax + bilinear sampling + head-weighted sum -> attn_pre
    sample_kernel<<<(MROWS * NHEAD * 32 + 255) / 256, 256>>>(refp, p_attn);
    // 5) tmp = attn_pre @ W_out + b_out + query            [80000 x 256 x 256]
    gemm128_kernel<2><<<dim3(256 / 128, MB128), 256>>>(p_attn, W_out, b_out, query, p_tmp, 256, 256);
    // 6) q = LN1(tmp)
    ln_kernel<<<(MROWS * 32 + 255) / 256, 256>>>(p_tmp, g1, be1, p_q);
    // 7) hidden = relu(q @ W1 + b1)                        [80000 x 1024 x 256]
    gemm128_kernel<1><<<dim3(DFFN / 128, MB128), 256>>>(p_q, W1, b1, nullptr, p_hidden, DFFN, 256);
    // 8) tmp = hidden @ W2 + b2 + q                        [80000 x 256 x 1024]
    gemm128_kernel<2><<<dim3(256 / 128, MB128), 256>>>(p_hidden, W2, b2, p_q, p_tmp, 256, DFFN);
    // 9) out = LN2(tmp)
    ln_kernel<<<(MROWS * 32 + 255) / 256, 256>>>(p_tmp, g2, be2, out);
}

// round 9
// speedup vs baseline: 2.4002x; 2.4002x over previous
#include <cuda_runtime.h>
#include <math.h>
#include <stdint.h>

// Problem constants (fixed by reference setup_inputs)
#define BATCH 8
#define LQ    10000
#define CDIM  256
#define NHEAD 8
#define NPNT  4
#define DFFN  1024
#define HIMG  100
#define WIMG  100
#define HDIM  32                 // CDIM / NHEAD
#define MROWS (BATCH * LQ)       // 80000

// ---------------------------------------------------------------------------
// Scratch (device globals; no cudaMalloc allowed)
// ---------------------------------------------------------------------------
__device__ float g_value [(size_t)MROWS * CDIM];
__device__ float g_off   [(size_t)MROWS * NHEAD * NPNT * 2];
__device__ float g_aw    [(size_t)MROWS * NHEAD * NPNT];
__device__ float g_attn  [(size_t)MROWS * CDIM];
__device__ float g_tmp   [(size_t)MROWS * CDIM];
__device__ float g_q     [(size_t)MROWS * CDIM];
__device__ float g_qr    [(size_t)MROWS * CDIM];     // tf32-rounded q
__device__ float g_hidden[(size_t)MROWS * DFFN];
__device__ float g_srcr  [(size_t)MROWS * CDIM];     // tf32-rounded src
__device__ float g_wvalT [CDIM * CDIM];              // [N,K] transposed+rounded
__device__ float g_woutT [CDIM * CDIM];
__device__ float g_w1T   [DFFN * CDIM];
__device__ float g_w2T   [CDIM * DFFN];

// ---------------------------------------------------------------------------
// Helpers
// ---------------------------------------------------------------------------
__device__ __forceinline__ float rna_tf32(float x) {
    float r;
    asm("cvt.rna.tf32.f32 %0, %1;" : "=f"(r) : "f"(x));
    return r;
}

// mma.sync tf32 16x8x8 (sm_80+ baseline feature; legal on generic compute_103)
__device__ __forceinline__ void mma_tf32(float c[4],
                                         uint32_t a0, uint32_t a1,
                                         uint32_t a2, uint32_t a3,
                                         uint32_t b0, uint32_t b1) {
    asm volatile(
        "mma.sync.aligned.m16n8k8.row.col.f32.tf32.tf32.f32 "
        "{%0,%1,%2,%3}, {%4,%5,%6,%7}, {%8,%9}, {%0,%1,%2,%3};"
        : "+f"(c[0]), "+f"(c[1]), "+f"(c[2]), "+f"(c[3])
        : "r"(a0), "r"(a1), "r"(a2), "r"(a3), "r"(b0), "r"(b1));
}

// ---------------------------------------------------------------------------
// Tensor-core tf32 GEMM via mma.sync:
//   C[M,N] = A[M,K] @ Bt[N,K]^T + bias (+relu|+residual)
// Block 128x128, BK=32, 256 threads (8 warps, each 64x32 = 4x4 mma tiles).
// Requires M%128==0, N%128==0, K%32==0. Inputs pre-rounded to tf32 (rna).
// EPI: 0=bias, 1=bias+relu, 2=bias+residual.  RND: round output to tf32.
// ---------------------------------------------------------------------------
#define SPAD 36   // 32 + 4 padding floats per smem row (conflict-free frags)

template<int EPI, int RND>
__global__ void __launch_bounds__(256) gemm_mma(
    const float* __restrict__ A, const float* __restrict__ Bt,
    const float* __restrict__ bias, const float* __restrict__ resid,
    float* __restrict__ C, int N, int K)
{
    __shared__ float As[128][SPAD];
    __shared__ float Bs[128][SPAD];

    const int tid  = threadIdx.x;
    const int wid  = tid >> 5;
    const int lane = tid & 31;
    const int gid  = lane >> 2;       // 0..7
    const int tig  = lane & 3;        // 0..3
    const int bm   = blockIdx.y * 128;
    const int bn   = blockIdx.x * 128;
    const int wm   = (wid & 1) * 64;  // warp row offset
    const int wn   = (wid >> 1) * 32; // warp col offset

    float acc[4][4][4];               // [mtile][ntile][reg]
    #pragma unroll
    for (int i = 0; i < 4; i++)
        #pragma unroll
        for (int j = 0; j < 4; j++)
            #pragma unroll
            for (int r = 0; r < 4; r++) acc[i][j][r] = 0.f;

    // global-load mapping: i = tid + 256*j -> row = i>>3 (0..127), quad = i&7
    const int NC = K >> 5;
    float4 pa[4], pb[4];
    #pragma unroll
    for (int j = 0; j < 4; j++) {
        int i = tid + 256 * j, r = i >> 3, q = i & 7;
        pa[j] = *(const float4*)&A [(size_t)(bm + r) * K + q * 4];
        pb[j] = *(const float4*)&Bt[(size_t)(bn + r) * K + q * 4];
    }

    for (int c = 0; c < NC; c++) {
        #pragma unroll
        for (int j = 0; j < 4; j++) {
            int i = tid + 256 * j, r = i >> 3, q = i & 7;
            *(float4*)&As[r][q * 4] = pa[j];
            *(float4*)&Bs[r][q * 4] = pb[j];
        }
        __syncthreads();

        if (c + 1 < NC) {
            const int k0 = (c + 1) << 5;
            #pragma unroll
            for (int j = 0; j < 4; j++) {
                int i = tid + 256 * j, r = i >> 3, q = i & 7;
                pa[j] = *(const float4*)&A [(size_t)(bm + r) * K + k0 + q * 4];
                pb[j] = *(const float4*)&Bt[(size_t)(bn + r) * K + k0 + q * 4];
            }
        }

        #pragma unroll
        for (int ks = 0; ks < 4; ks++) {
            const int kk = ks * 8;
            uint32_t bf[4][2];
            #pragma unroll
            for (int nt = 0; nt < 4; nt++) {
                const int n = wn + nt * 8 + gid;
                bf[nt][0] = __float_as_uint(Bs[n][kk + tig]);
                bf[nt][1] = __float_as_uint(Bs[n][kk + tig + 4]);
            }
            #pragma unroll
            for (int mt = 0; mt < 4; mt++) {
                const int m = wm + mt * 16;
                uint32_t a0 = __float_as_uint(As[m + gid    ][kk + tig]);
                uint32_t a1 = __float_as_uint(As[m + gid + 8][kk + tig]);
                uint32_t a2 = __float_as_uint(As[m + gid    ][kk + tig + 4]);
                uint32_t a3 = __float_as_uint(As[m + gid + 8][kk + tig + 4]);
                #pragma unroll
                for (int nt = 0; nt < 4; nt++)
                    mma_tf32(acc[mt][nt], a0, a1, a2, a3, bf[nt][0], bf[nt][1]);
            }
        }
        __syncthreads();
    }

    // Epilogue: c0/c1 -> row gid, cols 2*tig/2*tig+1; c2/c3 -> row gid+8.
    #pragma unroll
    for (int mt = 0; mt < 4; mt++) {
        const int r0 = bm + wm + mt * 16 + gid;
        const int r1 = r0 + 8;
        #pragma unroll
        for (int nt = 0; nt < 4; nt++) {
            const int cb = bn + wn + nt * 8 + 2 * tig;
            float2 v0 = make_float2(acc[mt][nt][0] + bias[cb],
                                    acc[mt][nt][1] + bias[cb + 1]);
            float2 v1 = make_float2(acc[mt][nt][2] + bias[cb],
                                    acc[mt][nt][3] + bias[cb + 1]);
            if (EPI == 1) {
                v0.x = fmaxf(v0.x, 0.f); v0.y = fmaxf(v0.y, 0.f);
                v1.x = fmaxf(v1.x, 0.f); v1.y = fmaxf(v1.y, 0.f);
            }
            if (EPI == 2) {
                float2 q0 = *(const float2*)&resid[(size_t)r0 * N + cb];
                float2 q1 = *(const float2*)&resid[(size_t)r1 * N + cb];
                v0.x += q0.x; v0.y += q0.y;
                v1.x += q1.x; v1.y += q1.y;
            }
            if (RND) {
                v0.x = rna_tf32(v0.x); v0.y = rna_tf32(v0.y);
                v1.x = rna_tf32(v1.x); v1.y = rna_tf32(v1.y);
            }
            *(float2*)&C[(size_t)r0 * N + cb] = v0;
            *(float2*)&C[(size_t)r1 * N + cb] = v1;
        }
    }
}

// ---------------------------------------------------------------------------
// Weight transpose + tf32 rounding: Wt[n*K+k] = rna(W[k*N+n])
// ---------------------------------------------------------------------------
__global__ void transpose_round_kernel(const float* __restrict__ W,
                                       float* __restrict__ Wt, int K, int N)
{
    __shared__ float t[32][33];
    const int k0 = blockIdx.y * 32, n0 = blockIdx.x * 32;
    const int tx = threadIdx.x, ty = threadIdx.y;
    #pragma unroll
    for (int i = ty; i < 32; i += 8)
        t[i][tx] = W[(size_t)(k0 + i) * N + n0 + tx];
    __syncthreads();
    #pragma unroll
    for (int i = ty; i < 32; i += 8)
        Wt[(size_t)(n0 + i) * K + k0 + tx] = rna_tf32(t[tx][i]);
}

// Elementwise tf32 rounding (vectorized)
__global__ void round_kernel(const float* __restrict__ x, float* __restrict__ y,
                             size_t n4)
{
    size_t i = (size_t)blockIdx.x * blockDim.x + threadIdx.x;
    if (i >= n4) return;
    float4 v = ((const float4*)x)[i];
    v.x = rna_tf32(v.x); v.y = rna_tf32(v.y);
    v.z = rna_tf32(v.z); v.w = rna_tf32(v.w);
    ((float4*)y)[i] = v;
}

// ---------------------------------------------------------------------------
// Small-N fp32 GEMM (N = 32 / 64): tile 64xN, BK=16, 256 threads, 4x4 micro.
// ---------------------------------------------------------------------------
__global__ void __launch_bounds__(256) gemm_small_kernel(
    const float* __restrict__ A, const float* __restrict__ W,
    const float* __restrict__ bias, float* __restrict__ C, int N, int K)
{
    __shared__ float As[16][64];
    __shared__ float Bs[16][64];

    const int tid = threadIdx.x;
    const int bm  = blockIdx.y * 64;
    const int tx  = tid & 15;
    const int ty  = tid >> 4;
    const int a_row = tid >> 2;
    const int a_k4  = (tid & 3) << 2;
    const int b_k   = tid >> 4;
    const int b_n4  = (tid & 15) << 2;
    const bool bvalid = b_n4 < N;

    float acc[4][4];
    #pragma unroll
    for (int i = 0; i < 4; i++)
        #pragma unroll
        for (int j = 0; j < 4; j++) acc[i][j] = 0.f;

    for (int k0 = 0; k0 < K; k0 += 16) {
        float4 av = *(const float4*)&A[(size_t)(bm + a_row) * K + k0 + a_k4];
        float4 bv = make_float4(0.f, 0.f, 0.f, 0.f);
        if (bvalid)
            bv = *(const float4*)&W[(size_t)(k0 + b_k) * N + b_n4];

        As[a_k4 + 0][a_row] = av.x;
        As[a_k4 + 1][a_row] = av.y;
        As[a_k4 + 2][a_row] = av.z;
        As[a_k4 + 3][a_row] = av.w;
        *(float4*)&Bs[b_k][b_n4] = bv;
        __syncthreads();

        #pragma unroll
        for (int k = 0; k < 16; ++k) {
            float4 a4 = *(const float4*)&As[k][ty * 4];
            float4 b4 = *(const float4*)&Bs[k][tx * 4];
            float ar[4] = {a4.x, a4.y, a4.z, a4.w};
            float br[4] = {b4.x, b4.y, b4.z, b4.w};
            #pragma unroll
            for (int i = 0; i < 4; i++)
                #pragma unroll
                for (int j = 0; j < 4; j++)
                    acc[i][j] = fmaf(ar[i], br[j], acc[i][j]);
        }
        __syncthreads();
    }

    #pragma unroll
    for (int i = 0; i < 4; i++) {
        const int row = bm + ty * 4 + i;
        #pragma unroll
        for (int j = 0; j < 4; j++) {
            const int col = tx * 4 + j;
            if (col < N)
                C[(size_t)row * N + col] = acc[i][j] + bias[col];
        }
    }
}

// ---------------------------------------------------------------------------
// Deformable sampling v2: one WARP per (b, q); lane covers (head = lane>>2,
// 8 channels = 2 x float4). Output rounded to tf32.
// ---------------------------------------------------------------------------
__global__ void __launch_bounds__(256) sample_kernel(
    const float* __restrict__ refpts, float* __restrict__ out)
{
    const int gtid = blockIdx.x * blockDim.x + threadIdx.x;
    const int bq   = gtid >> 5;          // warp id = (b,q)
    const int lane = gtid & 31;
    if (bq >= MROWS) return;

    const int h   = lane >> 2;           // head 0..7
    const int sub = lane & 3;            // channel quarter: 8 floats
    const int b   = bq / LQ;

    const float rx = refpts[(size_t)bq * 2 + 0] * (float)WIMG;
    const float ry = refpts[(size_t)bq * 2 + 1] * (float)HIMG;

    const float* awp = &g_aw[(size_t)bq * (NHEAD * NPNT) + h * NPNT];
    float a0 = awp[0], a1 = awp[1], a2 = awp[2], a3 = awp[3];
    float m  = fmaxf(fmaxf(a0, a1), fmaxf(a2, a3));
    float e0 = __expf(a0 - m), e1 = __expf(a1 - m);
    float e2 = __expf(a2 - m), e3 = __expf(a3 - m);
    float inv = 1.f / (e0 + e1 + e2 + e3);
    float aws[4] = {e0 * inv, e1 * inv, e2 * inv, e3 * inv};

    const float* offp  = &g_off[(size_t)bq * (NHEAD * NPNT * 2) + h * NPNT * 2];
    const float* vbase = &g_value[(size_t)b * LQ * CDIM + h * HDIM + sub * 8];

    float acc[8];
    #pragma unroll
    for (int i = 0; i < 8; i++) acc[i] = 0.f;

    #pragma unroll
    for (int p = 0; p < NPNT; p++) {
        float x = rx + offp[2 * p + 0] - 0.5f;
        float y = ry + offp[2 * p + 1] - 0.5f;
        float x0f = floorf(x), y0f = floorf(y);
        float lx = x - x0f, ly = y - y0f;
        int x0 = (int)x0f, y0 = (int)y0f;
        float w = aws[p];
        float wc[4] = {(1.f - lx) * (1.f - ly), lx * (1.f - ly),
                       (1.f - lx) * ly,         lx * ly};
        int xs[4] = {x0, x0 + 1, x0,     x0 + 1};
        int ys[4] = {y0, y0,     y0 + 1, y0 + 1};
        #pragma unroll
        for (int c = 0; c < 4; c++) {
            int xi = xs[c], yi = ys[c];
            if (xi >= 0 && xi < WIMG && yi >= 0 && yi < HIMG) {
                const float* vp = &vbase[(size_t)(yi * WIMG + xi) * CDIM];
                float4 v0 = *(const float4*)&vp[0];
                float4 v1 = *(const float4*)&vp[4];
                float ww = w * wc[c];
                acc[0] = fmaf(ww, v0.x, acc[0]);
                acc[1] = fmaf(ww, v0.y, acc[1]);
                acc[2] = fmaf(ww, v0.z, acc[2]);
                acc[3] = fmaf(ww, v0.w, acc[3]);
                acc[4] = fmaf(ww, v1.x, acc[4]);
                acc[5] = fmaf(ww, v1.y, acc[5]);
                acc[6] = fmaf(ww, v1.z, acc[6]);
                acc[7] = fmaf(ww, v1.w, acc[7]);
            }
        }
    }

    float* op = &out[(size_t)bq * CDIM + h * HDIM + sub * 8];
    float4 o0, o1;
    o0.x = rna_tf32(acc[0]); o0.y = rna_tf32(acc[1]);
    o0.z = rna_tf32(acc[2]); o0.w = rna_tf32(acc[3]);
    o1.x = rna_tf32(acc[4]); o1.y = rna_tf32(acc[5]);
    o1.z = rna_tf32(acc[6]); o1.w = rna_tf32(acc[7]);
    *(float4*)&op[0] = o0;
    *(float4*)&op[4] = o1;
}

// ---------------------------------------------------------------------------
// LayerNorm over C=256: one warp per row. Optionally emits tf32-rounded copy.
// ---------------------------------------------------------------------------
template<int WRITE_R>
__global__ void ln_kernel(const float* __restrict__ x,
                          const float* __restrict__ g,
                          const float* __restrict__ be,
                          float* __restrict__ y,
                          float* __restrict__ yr)
{
    const int gtid = blockIdx.x * blockDim.x + threadIdx.x;
    const int row  = gtid >> 5;
    const int lane = gtid & 31;
    if (row >= MROWS) return;

    const float* xr = x + (size_t)row * CDIM;
    float4 v0 = *(const float4*)&xr[lane * 4];
    float4 v1 = *(const float4*)&xr[128 + lane * 4];

    float s  = v0.x + v0.y + v0.z + v0.w + v1.x + v1.y + v1.z + v1.w;
    float sq = v0.x * v0.x + v0.y * v0.y + v0.z * v0.z + v0.w * v0.w
             + v1.x * v1.x + v1.y * v1.y + v1.z * v1.z + v1.w * v1.w;
    #pragma unroll
    for (int o = 16; o; o >>= 1) {
        s  += __shfl_xor_sync(0xffffffffu, s,  o);
        sq += __shfl_xor_sync(0xffffffffu, sq, o);
    }
    const float mean = s * (1.f / CDIM);
    const float var  = sq * (1.f / CDIM) - mean * mean;
    const float istd = rsqrtf(var + 1e-5f);

    float* yp = y + (size_t)row * CDIM;
    const int c0 = lane * 4;
    float4 o0, o1;
    o0.x = (v0.x - mean) * istd * g[c0 + 0] + be[c0 + 0];
    o0.y = (v0.y - mean) * istd * g[c0 + 1] + be[c0 + 1];
    o0.z = (v0.z - mean) * istd * g[c0 + 2] + be[c0 + 2];
    o0.w = (v0.w - mean) * istd * g[c0 + 3] + be[c0 + 3];
    o1.x = (v1.x - mean) * istd * g[128 + c0 + 0] + be[128 + c0 + 0];
    o1.y = (v1.y - mean) * istd * g[128 + c0 + 1] + be[128 + c0 + 1];
    o1.z = (v1.z - mean) * istd * g[128 + c0 + 2] + be[128 + c0 + 2];
    o1.w = (v1.w - mean) * istd * g[128 + c0 + 3] + be[128 + c0 + 3];
    *(float4*)&yp[c0]       = o0;
    *(float4*)&yp[128 + c0] = o1;
    if (WRITE_R) {
        float* rp = yr + (size_t)row * CDIM;
        float4 r0, r1;
        r0.x = rna_tf32(o0.x); r0.y = rna_tf32(o0.y);
        r0.z = rna_tf32(o0.z); r0.w = rna_tf32(o0.w);
        r1.x = rna_tf32(o1.x); r1.y = rna_tf32(o1.y);
        r1.z = rna_tf32(o1.z); r1.w = rna_tf32(o1.w);
        *(float4*)&rp[c0]       = r0;
        *(float4*)&rp[128 + c0] = r1;
    }
}

// ---------------------------------------------------------------------------
// Launch sequence (graph-capturable: kernel launches only)
// ---------------------------------------------------------------------------
extern "C" void kernel_launch(void* const* d_in, const int* in_sizes, int n_in,
                              void* d_out, int out_size)
{
    const float* query = (const float*)d_in[0];
    const float* src   = (const float*)d_in[1];
    const float* refp  = (const float*)d_in[2];
    const float* W_off = (const float*)d_in[5];
    const float* b_off = (const float*)d_in[6];
    const float* W_aw  = (const float*)d_in[7];
    const float* b_aw  = (const float*)d_in[8];
    const float* W_val = (const float*)d_in[9];
    const float* b_val = (const float*)d_in[10];
    const float* W_out = (const float*)d_in[11];
    const float* b_out = (const float*)d_in[12];
    const float* g1    = (const float*)d_in[13];
    const float* be1   = (const float*)d_in[14];
    const float* W1    = (const float*)d_in[15];
    const float* b1    = (const float*)d_in[16];
    const float* W2    = (const float*)d_in[17];
    const float* b2    = (const float*)d_in[18];
    const float* g2    = (const float*)d_in[19];
    const float* be2   = (const float*)d_in[20];
    float* out = (float*)d_out;

    float *p_value, *p_off, *p_aw, *p_attn, *p_tmp, *p_q, *p_qr, *p_hidden;
    float *p_srcr, *p_wvalT, *p_woutT, *p_w1T, *p_w2T;
    cudaGetSymbolAddress((void**)&p_value,  g_value);
    cudaGetSymbolAddress((void**)&p_off,    g_off);
    cudaGetSymbolAddress((void**)&p_aw,     g_aw);
    cudaGetSymbolAddress((void**)&p_attn,   g_attn);
    cudaGetSymbolAddress((void**)&p_tmp,    g_tmp);
    cudaGetSymbolAddress((void**)&p_q,      g_q);
    cudaGetSymbolAddress((void**)&p_qr,     g_qr);
    cudaGetSymbolAddress((void**)&p_hidden, g_hidden);
    cudaGetSymbolAddress((void**)&p_srcr,   g_srcr);
    cudaGetSymbolAddress((void**)&p_wvalT,  g_wvalT);
    cudaGetSymbolAddress((void**)&p_woutT,  g_woutT);
    cudaGetSymbolAddress((void**)&p_w1T,    g_w1T);
    cudaGetSymbolAddress((void**)&p_w2T,    g_w2T);

    const int MB128 = MROWS / 128;  // 625
    const int MB64  = MROWS / 64;   // 1250

    // 0) prep: round src; transpose+round weights
    {
        size_t n4 = (size_t)MROWS * CDIM / 4;
        round_kernel<<<(unsigned)((n4 + 255) / 256), 256>>>(src, p_srcr, n4);
        dim3 blk(32, 8);
        transpose_round_kernel<<<dim3(CDIM / 32, CDIM / 32), blk>>>(W_val, p_wvalT, CDIM, CDIM);
        transpose_round_kernel<<<dim3(CDIM / 32, CDIM / 32), blk>>>(W_out, p_woutT, CDIM, CDIM);
        transpose_round_kernel<<<dim3(DFFN / 32, CDIM / 32), blk>>>(W1, p_w1T, CDIM, DFFN);
        transpose_round_kernel<<<dim3(CDIM / 32, DFFN / 32), blk>>>(W2, p_w2T, DFFN, CDIM);
    }

    // 1) value = srcr @ W_val + b_val                     [80000 x 256 x 256]
    gemm_mma<0, 0><<<dim3(CDIM / 128, MB128), 256>>>(p_srcr, p_wvalT, b_val, nullptr, p_value, CDIM, CDIM);
    // 2) off logits (fp32 exact)                          [80000 x 64 x 256]
    gemm_small_kernel<<<dim3(1, MB64), 256>>>(query, W_off, b_off, p_off, 64, CDIM);
    // 3) aw logits (fp32 exact)                           [80000 x 32 x 256]
    gemm_small_kernel<<<dim3(1, MB64), 256>>>(query, W_aw, b_aw, p_aw, 32, CDIM);
    // 4) softmax + bilinear sampling -> attn (tf32-rounded); warp per (b,q)
    sample_kernel<<<(MROWS * 32 + 255) / 256, 256>>>(refp, p_attn);
    // 5) tmp = attn @ W_out + b_out + query               [80000 x 256 x 256]
    gemm_mma<2, 0><<<dim3(CDIM / 128, MB128), 256>>>(p_attn, p_woutT, b_out, query, p_tmp, CDIM, CDIM);
    // 6) q = LN1(tmp); qr = rna(q)
    ln_kernel<1><<<(MROWS * 32 + 255) / 256, 256>>>(p_tmp, g1, be1, p_q, p_qr);
    // 7) hidden = rna(relu(qr @ W1 + b1))                 [80000 x 1024 x 256]
    gemm_mma<1, 1><<<dim3(DFFN / 128, MB128), 256>>>(p_qr, p_w1T, b1, nullptr, p_hidden, DFFN, CDIM);
    // 8) tmp = hidden @ W2 + b2 + q                       [80000 x 256 x 1024]
    gemm_mma<2, 0><<<dim3(CDIM / 128, MB128), 256>>>(p_hidden, p_w2T, b2, p_q, p_tmp, CDIM, DFFN);
    // 9) out = LN2(tmp)
    ln_kernel<0><<<(MROWS * 32 + 255) / 256, 256>>>(p_tmp, g2, be2, out, nullptr);
}

// round 13
// speedup vs baseline: 3.4219x; 1.4257x over previous
#include <cuda_runtime.h>
#include <cuda_bf16.h>
#include <math.h>
#include <stdint.h>

// Problem constants (fixed by reference setup_inputs)
#define BATCH 8
#define LQ    10000
#define CDIM  256
#define NHEAD 8
#define NPNT  4
#define DFFN  1024
#define HIMG  100
#define WIMG  100
#define HDIM  32                 // CDIM / NHEAD
#define MROWS (BATCH * LQ)       // 80000

// ---------------------------------------------------------------------------
// Scratch (device globals; no cudaMalloc allowed)
// ---------------------------------------------------------------------------
__device__ float          g_value [(size_t)MROWS * CDIM];   // fp32 (sampler reads)
__device__ float          g_off   [(size_t)MROWS * NHEAD * NPNT * 2];
__device__ float          g_aw    [(size_t)MROWS * NHEAD * NPNT];
__device__ __nv_bfloat16  g_attn  [(size_t)MROWS * CDIM];
__device__ float          g_tmp   [(size_t)MROWS * CDIM];
__device__ float          g_q     [(size_t)MROWS * CDIM];
__device__ __nv_bfloat16  g_qr    [(size_t)MROWS * CDIM];
__device__ __nv_bfloat16  g_hidden[(size_t)MROWS * DFFN];
__device__ __nv_bfloat16  g_srcr  [(size_t)MROWS * CDIM];
__device__ __nv_bfloat16  g_wvalT [CDIM * CDIM];            // [N,K] transposed bf16
__device__ __nv_bfloat16  g_woutT [CDIM * CDIM];
__device__ __nv_bfloat16  g_w1T   [DFFN * CDIM];
__device__ __nv_bfloat16  g_w2T   [CDIM * DFFN];

// ---------------------------------------------------------------------------
// Helpers
// ---------------------------------------------------------------------------
__device__ __forceinline__ uint32_t pack_bf16(float lo, float hi) {
    uint32_t r;
    asm("cvt.rn.bf16x2.f32 %0, %1, %2;" : "=r"(r) : "f"(hi), "f"(lo));
    return r;
}

// mma.sync bf16 16x8x16 (sm_80+ baseline; legal on generic compute_103)
__device__ __forceinline__ void mma_bf16(float c[4],
                                         uint32_t a0, uint32_t a1,
                                         uint32_t a2, uint32_t a3,
                                         uint32_t b0, uint32_t b1) {
    asm volatile(
        "mma.sync.aligned.m16n8k16.row.col.f32.bf16.bf16.f32 "
        "{%0,%1,%2,%3}, {%4,%5,%6,%7}, {%8,%9}, {%0,%1,%2,%3};"
        : "+f"(c[0]), "+f"(c[1]), "+f"(c[2]), "+f"(c[3])
        : "r"(a0), "r"(a1), "r"(a2), "r"(a3), "r"(b0), "r"(b1));
}

// ---------------------------------------------------------------------------
// Tensor-core bf16 GEMM via mma.sync:
//   C[M,N] = A[M,K] @ Bt[N,K]^T + bias (+relu|+residual)
// Block 128x128, BK=64, 256 threads (8 warps, each 64x32 = 4x4 mma tiles).
// Smem row stride = 72 bf16 = 36 words (36 mod 32 = 4 -> conflict-free frags).
// Requires M%128==0, N%128==0, K%64==0.
// EPI: 0=bias, 1=bias+relu, 2=bias+residual.  OUTBF: 1 -> emit bf16 C.
// ---------------------------------------------------------------------------
#define RSW 36   // smem row stride in 32-bit words (72 bf16)

template<int EPI, int OUTBF>
__global__ void __launch_bounds__(256) gemm_bf16(
    const __nv_bfloat16* __restrict__ A, const __nv_bfloat16* __restrict__ Bt,
    const float* __restrict__ bias, const float* __restrict__ resid,
    void* __restrict__ Cv, int N, int K)
{
    __shared__ uint32_t As[128 * RSW];   // 18 KB
    __shared__ uint32_t Bs[128 * RSW];   // 18 KB

    const int tid  = threadIdx.x;
    const int wid  = tid >> 5;
    const int lane = tid & 31;
    const int gid  = lane >> 2;       // 0..7
    const int tig  = lane & 3;        // 0..3
    const int bm   = blockIdx.y * 128;
    const int bn   = blockIdx.x * 128;
    const int wm   = (wid & 1) * 64;  // warp row offset
    const int wn   = (wid >> 1) * 32; // warp col offset

    float acc[4][4][4];
    #pragma unroll
    for (int i = 0; i < 4; i++)
        #pragma unroll
        for (int j = 0; j < 4; j++)
            #pragma unroll
            for (int r = 0; r < 4; r++) acc[i][j][r] = 0.f;

    // global-load mapping: i = tid + 256*j -> row = i>>3, uint4-slot = i&7
    // (one uint4 = 8 bf16; BK=64 -> 8 slots per row)
    const int NC = K >> 6;
    uint4 pa[4], pb[4];
    #pragma unroll
    for (int j = 0; j < 4; j++) {
        int i = tid + 256 * j, r = i >> 3, s = i & 7;
        pa[j] = *(const uint4*)&A [(size_t)(bm + r) * K + s * 8];
        pb[j] = *(const uint4*)&Bt[(size_t)(bn + r) * K + s * 8];
    }

    for (int c = 0; c < NC; c++) {
        #pragma unroll
        for (int j = 0; j < 4; j++) {
            int i = tid + 256 * j, r = i >> 3, s = i & 7;
            *(uint4*)&As[r * RSW + s * 4] = pa[j];
            *(uint4*)&Bs[r * RSW + s * 4] = pb[j];
        }
        __syncthreads();

        if (c + 1 < NC) {
            const int k0 = (c + 1) << 6;
            #pragma unroll
            for (int j = 0; j < 4; j++) {
                int i = tid + 256 * j, r = i >> 3, s = i & 7;
                pa[j] = *(const uint4*)&A [(size_t)(bm + r) * K + k0 + s * 8];
                pb[j] = *(const uint4*)&Bt[(size_t)(bn + r) * K + k0 + s * 8];
            }
        }

        #pragma unroll
        for (int ks = 0; ks < 4; ks++) {
            const int kw = ks * 8;            // word offset of this k16 step
            uint32_t bf[4][2];
            #pragma unroll
            for (int nt = 0; nt < 4; nt++) {
                const int n = wn + nt * 8 + gid;
                bf[nt][0] = Bs[n * RSW + kw + tig];
                bf[nt][1] = Bs[n * RSW + kw + tig + 4];
            }
            #pragma unroll
            for (int mt = 0; mt < 4; mt++) {
                const int m = wm + mt * 16;
                uint32_t a0 = As[(m + gid    ) * RSW + kw + tig];
                uint32_t a1 = As[(m + gid + 8) * RSW + kw + tig];
                uint32_t a2 = As[(m + gid    ) * RSW + kw + tig + 4];
                uint32_t a3 = As[(m + gid + 8) * RSW + kw + tig + 4];
                #pragma unroll
                for (int nt = 0; nt < 4; nt++)
                    mma_bf16(acc[mt][nt], a0, a1, a2, a3, bf[nt][0], bf[nt][1]);
            }
        }
        __syncthreads();
    }

    // Epilogue: c0/c1 -> row gid, cols 2*tig/2*tig+1; c2/c3 -> row gid+8.
    #pragma unroll
    for (int mt = 0; mt < 4; mt++) {
        const int r0 = bm + wm + mt * 16 + gid;
        const int r1 = r0 + 8;
        #pragma unroll
        for (int nt = 0; nt < 4; nt++) {
            const int cb = bn + wn + nt * 8 + 2 * tig;
            float2 v0 = make_float2(acc[mt][nt][0] + bias[cb],
                                    acc[mt][nt][1] + bias[cb + 1]);
            float2 v1 = make_float2(acc[mt][nt][2] + bias[cb],
                                    acc[mt][nt][3] + bias[cb + 1]);
            if (EPI == 1) {
                v0.x = fmaxf(v0.x, 0.f); v0.y = fmaxf(v0.y, 0.f);
                v1.x = fmaxf(v1.x, 0.f); v1.y = fmaxf(v1.y, 0.f);
            }
            if (EPI == 2) {
                float2 q0 = *(const float2*)&resid[(size_t)r0 * N + cb];
                float2 q1 = *(const float2*)&resid[(size_t)r1 * N + cb];
                v0.x += q0.x; v0.y += q0.y;
                v1.x += q1.x; v1.y += q1.y;
            }
            if (OUTBF) {
                __nv_bfloat16* C = (__nv_bfloat16*)Cv;
                *(uint32_t*)&C[(size_t)r0 * N + cb] = pack_bf16(v0.x, v0.y);
                *(uint32_t*)&C[(size_t)r1 * N + cb] = pack_bf16(v1.x, v1.y);
            } else {
                float* C = (float*)Cv;
                *(float2*)&C[(size_t)r0 * N + cb] = v0;
                *(float2*)&C[(size_t)r1 * N + cb] = v1;
            }
        }
    }
}

// ---------------------------------------------------------------------------
// Weight transpose to bf16: Wt[n*K+k] = bf16(W[k*N+n])
// ---------------------------------------------------------------------------
__global__ void transpose_bf16_kernel(const float* __restrict__ W,
                                      __nv_bfloat16* __restrict__ Wt,
                                      int K, int N)
{
    __shared__ float t[32][33];
    const int k0 = blockIdx.y * 32, n0 = blockIdx.x * 32;
    const int tx = threadIdx.x, ty = threadIdx.y;
    #pragma unroll
    for (int i = ty; i < 32; i += 8)
        t[i][tx] = W[(size_t)(k0 + i) * N + n0 + tx];
    __syncthreads();
    #pragma unroll
    for (int i = ty; i < 32; i += 8)
        Wt[(size_t)(n0 + i) * K + k0 + tx] = __float2bfloat16_rn(t[tx][i]);
}

// Elementwise f32 -> bf16 convert (vectorized: 4 per thread)
__global__ void cvt_bf16_kernel(const float* __restrict__ x,
                                __nv_bfloat16* __restrict__ y, size_t n4)
{
    size_t i = (size_t)blockIdx.x * blockDim.x + threadIdx.x;
    if (i >= n4) return;
    float4 v = ((const float4*)x)[i];
    uint2 o;
    o.x = pack_bf16(v.x, v.y);
    o.y = pack_bf16(v.z, v.w);
    ((uint2*)y)[i] = o;
}

// ---------------------------------------------------------------------------
// Small-N fp32 GEMM (N = 32 / 64) — exact (feeds floor()-sensitive coords).
// ---------------------------------------------------------------------------
__global__ void __launch_bounds__(256) gemm_small_kernel(
    const float* __restrict__ A, const float* __restrict__ W,
    const float* __restrict__ bias, float* __restrict__ C, int N, int K)
{
    __shared__ float As[16][64];
    __shared__ float Bs[16][64];

    const int tid = threadIdx.x;
    const int bm  = blockIdx.y * 64;
    const int tx  = tid & 15;
    const int ty  = tid >> 4;
    const int a_row = tid >> 2;
    const int a_k4  = (tid & 3) << 2;
    const int b_k   = tid >> 4;
    const int b_n4  = (tid & 15) << 2;
    const bool bvalid = b_n4 < N;

    float acc[4][4];
    #pragma unroll
    for (int i = 0; i < 4; i++)
        #pragma unroll
        for (int j = 0; j < 4; j++) acc[i][j] = 0.f;

    for (int k0 = 0; k0 < K; k0 += 16) {
        float4 av = *(const float4*)&A[(size_t)(bm + a_row) * K + k0 + a_k4];
        float4 bv = make_float4(0.f, 0.f, 0.f, 0.f);
        if (bvalid)
            bv = *(const float4*)&W[(size_t)(k0 + b_k) * N + b_n4];

        As[a_k4 + 0][a_row] = av.x;
        As[a_k4 + 1][a_row] = av.y;
        As[a_k4 + 2][a_row] = av.z;
        As[a_k4 + 3][a_row] = av.w;
        *(float4*)&Bs[b_k][b_n4] = bv;
        __syncthreads();

        #pragma unroll
        for (int k = 0; k < 16; ++k) {
            float4 a4 = *(const float4*)&As[k][ty * 4];
            float4 b4 = *(const float4*)&Bs[k][tx * 4];
            float ar[4] = {a4.x, a4.y, a4.z, a4.w};
            float br[4] = {b4.x, b4.y, b4.z, b4.w};
            #pragma unroll
            for (int i = 0; i < 4; i++)
                #pragma unroll
                for (int j = 0; j < 4; j++)
                    acc[i][j] = fmaf(ar[i], br[j], acc[i][j]);
        }
        __syncthreads();
    }

    #pragma unroll
    for (int i = 0; i < 4; i++) {
        const int row = bm + ty * 4 + i;
        #pragma unroll
        for (int j = 0; j < 4; j++) {
            const int col = tx * 4 + j;
            if (col < N)
                C[(size_t)row * N + col] = acc[i][j] + bias[col];
        }
    }
}

// ---------------------------------------------------------------------------
// Deformable sampling v2: one WARP per (b, q); lane = (head = lane>>2,
// 8 channels via 2 x float4). Emits bf16 attn (one uint4 per lane).
// ---------------------------------------------------------------------------
__global__ void __launch_bounds__(256) sample_kernel(
    const float* __restrict__ refpts, __nv_bfloat16* __restrict__ out)
{
    const int gtid = blockIdx.x * blockDim.x + threadIdx.x;
    const int bq   = gtid >> 5;
    const int lane = gtid & 31;
    if (bq >= MROWS) return;

    const int h   = lane >> 2;
    const int sub = lane & 3;
    const int b   = bq / LQ;

    const float rx = refpts[(size_t)bq * 2 + 0] * (float)WIMG;
    const float ry = refpts[(size_t)bq * 2 + 1] * (float)HIMG;

    const float* awp = &g_aw[(size_t)bq * (NHEAD * NPNT) + h * NPNT];
    float a0 = awp[0], a1 = awp[1], a2 = awp[2], a3 = awp[3];
    float m  = fmaxf(fmaxf(a0, a1), fmaxf(a2, a3));
    float e0 = __expf(a0 - m), e1 = __expf(a1 - m);
    float e2 = __expf(a2 - m), e3 = __expf(a3 - m);
    float inv = 1.f / (e0 + e1 + e2 + e3);
    float aws[4] = {e0 * inv, e1 * inv, e2 * inv, e3 * inv};

    const float* offp  = &g_off[(size_t)bq * (NHEAD * NPNT * 2) + h * NPNT * 2];
    const float* vbase = &g_value[(size_t)b * LQ * CDIM + h * HDIM + sub * 8];

    float acc[8];
    #pragma unroll
    for (int i = 0; i < 8; i++) acc[i] = 0.f;

    #pragma unroll
    for (int p = 0; p < NPNT; p++) {
        float x = rx + offp[2 * p + 0] - 0.5f;
        float y = ry + offp[2 * p + 1] - 0.5f;
        float x0f = floorf(x), y0f = floorf(y);
        float lx = x - x0f, ly = y - y0f;
        int x0 = (int)x0f, y0 = (int)y0f;
        float w = aws[p];
        float wc[4] = {(1.f - lx) * (1.f - ly), lx * (1.f - ly),
                       (1.f - lx) * ly,         lx * ly};
        int xs[4] = {x0, x0 + 1, x0,     x0 + 1};
        int ys[4] = {y0, y0,     y0 + 1, y0 + 1};
        #pragma unroll
        for (int c = 0; c < 4; c++) {
            int xi = xs[c], yi = ys[c];
            if (xi >= 0 && xi < WIMG && yi >= 0 && yi < HIMG) {
                const float* vp = &vbase[(size_t)(yi * WIMG + xi) * CDIM];
                float4 v0 = *(const float4*)&vp[0];
                float4 v1 = *(const float4*)&vp[4];
                float ww = w * wc[c];
                acc[0] = fmaf(ww, v0.x, acc[0]);
                acc[1] = fmaf(ww, v0.y, acc[1]);
                acc[2] = fmaf(ww, v0.z, acc[2]);
                acc[3] = fmaf(ww, v0.w, acc[3]);
                acc[4] = fmaf(ww, v1.x, acc[4]);
                acc[5] = fmaf(ww, v1.y, acc[5]);
                acc[6] = fmaf(ww, v1.z, acc[6]);
                acc[7] = fmaf(ww, v1.w, acc[7]);
            }
        }
    }

    uint4 o;
    o.x = pack_bf16(acc[0], acc[1]);
    o.y = pack_bf16(acc[2], acc[3]);
    o.z = pack_bf16(acc[4], acc[5]);
    o.w = pack_bf16(acc[6], acc[7]);
    *(uint4*)&out[(size_t)bq * CDIM + h * HDIM + sub * 8] = o;
}

// ---------------------------------------------------------------------------
// LayerNorm over C=256: one warp per row. Optionally emits bf16 copy.
// ---------------------------------------------------------------------------
template<int WRITE_R>
__global__ void ln_kernel(const float* __restrict__ x,
                          const float* __restrict__ g,
                          const float* __restrict__ be,
                          float* __restrict__ y,
                          __nv_bfloat16* __restrict__ yr)
{
    const int gtid = blockIdx.x * blockDim.x + threadIdx.x;
    const int row  = gtid >> 5;
    const int lane = gtid & 31;
    if (row >= MROWS) return;

    const float* xr = x + (size_t)row * CDIM;
    float4 v0 = *(const float4*)&xr[lane * 4];
    float4 v1 = *(const float4*)&xr[128 + lane * 4];

    float s  = v0.x + v0.y + v0.z + v0.w + v1.x + v1.y + v1.z + v1.w;
    float sq = v0.x * v0.x + v0.y * v0.y + v0.z * v0.z + v0.w * v0.w
             + v1.x * v1.x + v1.y * v1.y + v1.z * v1.z + v1.w * v1.w;
    #pragma unroll
    for (int o = 16; o; o >>= 1) {
        s  += __shfl_xor_sync(0xffffffffu, s,  o);
        sq += __shfl_xor_sync(0xffffffffu, sq, o);
    }
    const float mean = s * (1.f / CDIM);
    const float var  = sq * (1.f / CDIM) - mean * mean;
    const float istd = rsqrtf(var + 1e-5f);

    float* yp = y + (size_t)row * CDIM;
    const int c0 = lane * 4;
    float4 o0, o1;
    o0.x = (v0.x - mean) * istd * g[c0 + 0] + be[c0 + 0];
    o0.y = (v0.y - mean) * istd * g[c0 + 1] + be[c0 + 1];
    o0.z = (v0.z - mean) * istd * g[c0 + 2] + be[c0 + 2];
    o0.w = (v0.w - mean) * istd * g[c0 + 3] + be[c0 + 3];
    o1.x = (v1.x - mean) * istd * g[128 + c0 + 0] + be[128 + c0 + 0];
    o1.y = (v1.y - mean) * istd * g[128 + c0 + 1] + be[128 + c0 + 1];
    o1.z = (v1.z - mean) * istd * g[128 + c0 + 2] + be[128 + c0 + 2];
    o1.w = (v1.w - mean) * istd * g[128 + c0 + 3] + be[128 + c0 + 3];
    *(float4*)&yp[c0]       = o0;
    *(float4*)&yp[128 + c0] = o1;
    if (WRITE_R) {
        __nv_bfloat16* rp = yr + (size_t)row * CDIM;
        uint2 r0, r1;
        r0.x = pack_bf16(o0.x, o0.y); r0.y = pack_bf16(o0.z, o0.w);
        r1.x = pack_bf16(o1.x, o1.y); r1.y = pack_bf16(o1.z, o1.w);
        *(uint2*)&rp[c0]       = r0;
        *(uint2*)&rp[128 + c0] = r1;
    }
}

// ---------------------------------------------------------------------------
// Launch sequence (graph-capturable: kernel launches only)
// ---------------------------------------------------------------------------
extern "C" void kernel_launch(void* const* d_in, const int* in_sizes, int n_in,
                              void* d_out, int out_size)
{
    const float* query = (const float*)d_in[0];
    const float* src   = (const float*)d_in[1];
    const float* refp  = (const float*)d_in[2];
    const float* W_off = (const float*)d_in[5];
    const float* b_off = (const float*)d_in[6];
    const float* W_aw  = (const float*)d_in[7];
    const float* b_aw  = (const float*)d_in[8];
    const float* W_val = (const float*)d_in[9];
    const float* b_val = (const float*)d_in[10];
    const float* W_out = (const float*)d_in[11];
    const float* b_out = (const float*)d_in[12];
    const float* g1    = (const float*)d_in[13];
    const float* be1   = (const float*)d_in[14];
    const float* W1    = (const float*)d_in[15];
    const float* b1    = (const float*)d_in[16];
    const float* W2    = (const float*)d_in[17];
    const float* b2    = (const float*)d_in[18];
    const float* g2    = (const float*)d_in[19];
    const float* be2   = (const float*)d_in[20];
    float* out = (float*)d_out;

    float *p_value, *p_off, *p_aw, *p_tmp, *p_q;
    __nv_bfloat16 *p_attn, *p_qr, *p_hidden, *p_srcr;
    __nv_bfloat16 *p_wvalT, *p_woutT, *p_w1T, *p_w2T;
    cudaGetSymbolAddress((void**)&p_value,  g_value);
    cudaGetSymbolAddress((void**)&p_off,    g_off);
    cudaGetSymbolAddress((void**)&p_aw,     g_aw);
    cudaGetSymbolAddress((void**)&p_attn,   g_attn);
    cudaGetSymbolAddress((void**)&p_tmp,    g_tmp);
    cudaGetSymbolAddress((void**)&p_q,      g_q);
    cudaGetSymbolAddress((void**)&p_qr,     g_qr);
    cudaGetSymbolAddress((void**)&p_hidden, g_hidden);
    cudaGetSymbolAddress((void**)&p_srcr,   g_srcr);
    cudaGetSymbolAddress((void**)&p_wvalT,  g_wvalT);
    cudaGetSymbolAddress((void**)&p_woutT,  g_woutT);
    cudaGetSymbolAddress((void**)&p_w1T,    g_w1T);
    cudaGetSymbolAddress((void**)&p_w2T,    g_w2T);

    const int MB128 = MROWS / 128;  // 625
    const int MB64  = MROWS / 64;   // 1250

    // 0) prep: convert src to bf16; transpose weights to bf16 [N,K]
    {
        size_t n4 = (size_t)MROWS * CDIM / 4;
        cvt_bf16_kernel<<<(unsigned)((n4 + 255) / 256), 256>>>(src, p_srcr, n4);
        dim3 blk(32, 8);
        transpose_bf16_kernel<<<dim3(CDIM / 32, CDIM / 32), blk>>>(W_val, p_wvalT, CDIM, CDIM);
        transpose_bf16_kernel<<<dim3(CDIM / 32, CDIM / 32), blk>>>(W_out, p_woutT, CDIM, CDIM);
        transpose_bf16_kernel<<<dim3(DFFN / 32, CDIM / 32), blk>>>(W1, p_w1T, CDIM, DFFN);
        transpose_bf16_kernel<<<dim3(CDIM / 32, DFFN / 32), blk>>>(W2, p_w2T, DFFN, CDIM);
    }

    // 1) value = srcr @ W_val + b_val  (f32 out)           [80000 x 256 x 256]
    gemm_bf16<0, 0><<<dim3(CDIM / 128, MB128), 256>>>(p_srcr, p_wvalT, b_val, nullptr, p_value, CDIM, CDIM);
    // 2) off logits (fp32 exact — feeds floor())           [80000 x 64 x 256]
    gemm_small_kernel<<<dim3(1, MB64), 256>>>(query, W_off, b_off, p_off, 64, CDIM);
    // 3) aw logits (fp32 exact)                            [80000 x 32 x 256]
    gemm_small_kernel<<<dim3(1, MB64), 256>>>(query, W_aw, b_aw, p_aw, 32, CDIM);
    // 4) softmax + bilinear sampling -> attn (bf16)
    sample_kernel<<<(MROWS * 32 + 255) / 256, 256>>>(refp, p_attn);
    // 5) tmp = attn @ W_out + b_out + query (f32 out)      [80000 x 256 x 256]
    gemm_bf16<2, 0><<<dim3(CDIM / 128, MB128), 256>>>(p_attn, p_woutT, b_out, query, p_tmp, CDIM, CDIM);
    // 6) q = LN1(tmp); qr = bf16(q)
    ln_kernel<1><<<(MROWS * 32 + 255) / 256, 256>>>(p_tmp, g1, be1, p_q, p_qr);
    // 7) hidden = bf16(relu(qr @ W1 + b1))                 [80000 x 1024 x 256]
    gemm_bf16<1, 1><<<dim3(DFFN / 128, MB128), 256>>>(p_qr, p_w1T, b1, nullptr, p_hidden, DFFN, CDIM);
    // 8) tmp = hidden @ W2 + b2 + q (f32 out)              [80000 x 256 x 1024]
    gemm_bf16<2, 0><<<dim3(CDIM / 128, MB128), 256>>>(p_hidden, p_w2T, b2, p_q, p_tmp, CDIM, DFFN);
    // 9) out = LN2(tmp)
    ln_kernel<0><<<(MROWS * 32 + 255) / 256, 256>>>(p_tmp, g2, be2, out, nullptr);
}

// round 16
// speedup vs baseline: 3.5473x; 1.0366x over previous
#include <cuda_runtime.h>
#include <cuda_bf16.h>
#include <math.h>
#include <stdint.h>

// Problem constants (fixed by reference setup_inputs)
#define BATCH 8
#define LQ    10000
#define CDIM  256
#define NHEAD 8
#define NPNT  4
#define DFFN  1024
#define HIMG  100
#define WIMG  100
#define HDIM  32                 // CDIM / NHEAD
#define MROWS (BATCH * LQ)       // 80000

// ---------------------------------------------------------------------------
// Scratch (device globals; no cudaMalloc allowed)
// ---------------------------------------------------------------------------
__device__ float          g_value [(size_t)MROWS * CDIM];   // fp32 (sampler reads)
__device__ float          g_off   [(size_t)MROWS * NHEAD * NPNT * 2];
__device__ float          g_aw    [(size_t)MROWS * NHEAD * NPNT];
__device__ __nv_bfloat16  g_attn  [(size_t)MROWS * CDIM];
__device__ float          g_tmp   [(size_t)MROWS * CDIM];
__device__ float          g_q     [(size_t)MROWS * CDIM];
__device__ __nv_bfloat16  g_qr    [(size_t)MROWS * CDIM];
__device__ __nv_bfloat16  g_hidden[(size_t)MROWS * DFFN];
__device__ __nv_bfloat16  g_srcr  [(size_t)MROWS * CDIM];
__device__ __nv_bfloat16  g_wvalT [CDIM * CDIM];            // [N,K] transposed bf16
__device__ __nv_bfloat16  g_woutT [CDIM * CDIM];
__device__ __nv_bfloat16  g_w1T   [DFFN * CDIM];
__device__ __nv_bfloat16  g_w2T   [CDIM * DFFN];

// ---------------------------------------------------------------------------
// Helpers
// ---------------------------------------------------------------------------
__device__ __forceinline__ uint32_t pack_bf16(float lo, float hi) {
    uint32_t r;
    asm("cvt.rn.bf16x2.f32 %0, %1, %2;" : "=r"(r) : "f"(hi), "f"(lo));
    return r;
}
__device__ __forceinline__ uint32_t smem_u32(const void* p) {
    uint32_t a;
    asm("{ .reg .u64 t; cvta.to.shared.u64 t, %1; cvt.u32.u64 %0, t; }"
        : "=r"(a) : "l"(p));
    return a;
}

// mma.sync bf16 16x8x16 (sm_80+ baseline; legal on generic compute_103)
__device__ __forceinline__ void mma_bf16(float c[4],
                                         uint32_t a0, uint32_t a1,
                                         uint32_t a2, uint32_t a3,
                                         uint32_t b0, uint32_t b1) {
    asm volatile(
        "mma.sync.aligned.m16n8k16.row.col.f32.bf16.bf16.f32 "
        "{%0,%1,%2,%3}, {%4,%5,%6,%7}, {%8,%9}, {%0,%1,%2,%3};"
        : "+f"(c[0]), "+f"(c[1]), "+f"(c[2]), "+f"(c[3])
        : "r"(a0), "r"(a1), "r"(a2), "r"(a3), "r"(b0), "r"(b1));
}
// ldmatrix x4 (sm_75+ baseline)
__device__ __forceinline__ void ldsm4(uint32_t& r0, uint32_t& r1,
                                      uint32_t& r2, uint32_t& r3, uint32_t addr) {
    asm volatile("ldmatrix.sync.aligned.m8n8.x4.shared.b16 {%0,%1,%2,%3}, [%4];"
                 : "=r"(r0), "=r"(r1), "=r"(r2), "=r"(r3) : "r"(addr));
}

// ---------------------------------------------------------------------------
// Tensor-core bf16 GEMM, cp.async double-buffered, ldmatrix frag loads:
//   C[M,N] = A[M,K] @ Bt[N,K]^T + bias (+relu|+residual)
// Block 128x128, BK=32, 256 threads (8 warps, each 64x32 = 4x4 mma tiles).
// Smem row stride = 20 words (64B data + 16B pad): 8 rows spaced 20 words hit
// 8 distinct 4-word bank slots -> conflict-free ldmatrix & cp.async stores.
// Requires M%128==0, N%128==0, K%32==0.
// EPI: 0=bias, 1=bias+relu, 2=bias+residual.  OUTBF: 1 -> emit bf16 C.
// ---------------------------------------------------------------------------
#define RS2 20   // smem row stride in 32-bit words (40 bf16)

template<int EPI, int OUTBF>
__global__ void __launch_bounds__(256) gemm_bf16(
    const __nv_bfloat16* __restrict__ A, const __nv_bfloat16* __restrict__ Bt,
    const float* __restrict__ bias, const float* __restrict__ resid,
    void* __restrict__ Cv, int N, int K)
{
    __shared__ uint32_t As[2][128 * RS2];   // 2 x 10 KB
    __shared__ uint32_t Bs[2][128 * RS2];   // 2 x 10 KB

    const int tid  = threadIdx.x;
    const int wid  = tid >> 5;
    const int lane = tid & 31;
    const int gid  = lane >> 2;       // 0..7
    const int tig  = lane & 3;        // 0..3
    const int bm   = blockIdx.y * 128;
    const int bn   = blockIdx.x * 128;
    const int wm   = (wid & 1) * 64;  // warp row offset
    const int wn   = (wid >> 1) * 32; // warp col offset
    const int lg   = lane >> 3;       // ldmatrix group 0..3
    const int lj   = lane & 7;        // row within group

    float acc[4][4][4];
    #pragma unroll
    for (int i = 0; i < 4; i++)
        #pragma unroll
        for (int j = 0; j < 4; j++)
            #pragma unroll
            for (int r = 0; r < 4; r++) acc[i][j][r] = 0.f;

    const int NC = K >> 5;

    // cp.async one BK=32 chunk (A+B) into buffer `buf`.
    // i = tid + 256*j -> row = i>>2 (0..127), 16B slot = i&3.
    auto copy_chunk = [&](int k0, int buf) {
        #pragma unroll
        for (int j = 0; j < 2; j++) {
            int i = tid + 256 * j, r = i >> 2, s = i & 3;
            uint32_t dA = smem_u32(&As[buf][r * RS2 + s * 4]);
            uint32_t dB = smem_u32(&Bs[buf][r * RS2 + s * 4]);
            const void* gA = &A [(size_t)(bm + r) * K + k0 + s * 8];
            const void* gB = &Bt[(size_t)(bn + r) * K + k0 + s * 8];
            asm volatile("cp.async.cg.shared.global [%0], [%1], 16;" :: "r"(dA), "l"(gA));
            asm volatile("cp.async.cg.shared.global [%0], [%1], 16;" :: "r"(dB), "l"(gB));
        }
        asm volatile("cp.async.commit_group;" ::: "memory");
    };

    // prologue: chunk 0 into buffer 0
    copy_chunk(0, 0);
    asm volatile("cp.async.wait_group 0;" ::: "memory");
    __syncthreads();

    int p = 0;
    for (int c = 0; c < NC; c++) {
        if (c + 1 < NC) copy_chunk((c + 1) << 5, p ^ 1);

        const uint32_t* as = As[p];
        const uint32_t* bs = Bs[p];
        #pragma unroll
        for (int ks = 0; ks < 2; ks++) {
            const int kw = ks * 8;
            uint32_t bf[4][2];
            #pragma unroll
            for (int pr = 0; pr < 2; pr++) {
                // groups: g0 rows n+j k0-7 | g1 rows n+j k8-15
                //         g2 rows n+8+j k0-7 | g3 rows n+8+j k8-15
                int row  = wn + pr * 16 + (lg >> 1) * 8 + lj;
                int word = kw + (lg & 1) * 4;
                uint32_t r0, r1, r2, r3;
                ldsm4(r0, r1, r2, r3, smem_u32(&bs[row * RS2 + word]));
                bf[2 * pr][0] = r0;  bf[2 * pr][1] = r1;
                bf[2 * pr + 1][0] = r2;  bf[2 * pr + 1][1] = r3;
            }
            #pragma unroll
            for (int mt = 0; mt < 4; mt++) {
                // groups: g0 rows m+j k0-7 | g1 rows m+8+j k0-7
                //         g2 rows m+j k8-15 | g3 rows m+8+j k8-15
                int row  = wm + mt * 16 + (lg & 1) * 8 + lj;
                int word = kw + (lg >> 1) * 4;
                uint32_t a0, a1, a2, a3;
                ldsm4(a0, a1, a2, a3, smem_u32(&as[row * RS2 + word]));
                #pragma unroll
                for (int nt = 0; nt < 4; nt++)
                    mma_bf16(acc[mt][nt], a0, a1, a2, a3, bf[nt][0], bf[nt][1]);
            }
        }

        asm volatile("cp.async.wait_group 0;" ::: "memory");
        __syncthreads();
        p ^= 1;
    }

    // Epilogue: c0/c1 -> row gid, cols 2*tig/2*tig+1; c2/c3 -> row gid+8.
    #pragma unroll
    for (int mt = 0; mt < 4; mt++) {
        const int r0 = bm + wm + mt * 16 + gid;
        const int r1 = r0 + 8;
        #pragma unroll
        for (int nt = 0; nt < 4; nt++) {
            const int cb = bn + wn + nt * 8 + 2 * tig;
            float2 v0 = make_float2(acc[mt][nt][0] + bias[cb],
                                    acc[mt][nt][1] + bias[cb + 1]);
            float2 v1 = make_float2(acc[mt][nt][2] + bias[cb],
                                    acc[mt][nt][3] + bias[cb + 1]);
            if (EPI == 1) {
                v0.x = fmaxf(v0.x, 0.f); v0.y = fmaxf(v0.y, 0.f);
                v1.x = fmaxf(v1.x, 0.f); v1.y = fmaxf(v1.y, 0.f);
            }
            if (EPI == 2) {
                float2 q0 = *(const float2*)&resid[(size_t)r0 * N + cb];
                float2 q1 = *(const float2*)&resid[(size_t)r1 * N + cb];
                v0.x += q0.x; v0.y += q0.y;
                v1.x += q1.x; v1.y += q1.y;
            }
            if (OUTBF) {
                __nv_bfloat16* C = (__nv_bfloat16*)Cv;
                *(uint32_t*)&C[(size_t)r0 * N + cb] = pack_bf16(v0.x, v0.y);
                *(uint32_t*)&C[(size_t)r1 * N + cb] = pack_bf16(v1.x, v1.y);
            } else {
                float* C = (float*)Cv;
                *(float2*)&C[(size_t)r0 * N + cb] = v0;
                *(float2*)&C[(size_t)r1 * N + cb] = v1;
            }
        }
    }
}

// ---------------------------------------------------------------------------
// Weight transpose to bf16: Wt[n*K+k] = bf16(W[k*N+n])
// ---------------------------------------------------------------------------
__global__ void transpose_bf16_kernel(const float* __restrict__ W,
                                      __nv_bfloat16* __restrict__ Wt,
                                      int K, int N)
{
    __shared__ float t[32][33];
    const int k0 = blockIdx.y * 32, n0 = blockIdx.x * 32;
    const int tx = threadIdx.x, ty = threadIdx.y;
    #pragma unroll
    for (int i = ty; i < 32; i += 8)
        t[i][tx] = W[(size_t)(k0 + i) * N + n0 + tx];
    __syncthreads();
    #pragma unroll
    for (int i = ty; i < 32; i += 8)
        Wt[(size_t)(n0 + i) * K + k0 + tx] = __float2bfloat16_rn(t[tx][i]);
}

// Elementwise f32 -> bf16 convert (vectorized: 4 per thread)
__global__ void cvt_bf16_kernel(const float* __restrict__ x,
                                __nv_bfloat16* __restrict__ y, size_t n4)
{
    size_t i = (size_t)blockIdx.x * blockDim.x + threadIdx.x;
    if (i >= n4) return;
    float4 v = ((const float4*)x)[i];
    uint2 o;
    o.x = pack_bf16(v.x, v.y);
    o.y = pack_bf16(v.z, v.w);
    ((uint2*)y)[i] = o;
}

// ---------------------------------------------------------------------------
// Small-N fp32 GEMM (N = 32 / 64) — exact (feeds floor()-sensitive coords).
// ---------------------------------------------------------------------------
__global__ void __launch_bounds__(256) gemm_small_kernel(
    const float* __restrict__ A, const float* __restrict__ W,
    const float* __restrict__ bias, float* __restrict__ C, int N, int K)
{
    __shared__ float As[16][64];
    __shared__ float Bs[16][64];

    const int tid = threadIdx.x;
    const int bm  = blockIdx.y * 64;
    const int tx  = tid & 15;
    const int ty  = tid >> 4;
    const int a_row = tid >> 2;
    const int a_k4  = (tid & 3) << 2;
    const int b_k   = tid >> 4;
    const int b_n4  = (tid & 15) << 2;
    const bool bvalid = b_n4 < N;

    float acc[4][4];
    #pragma unroll
    for (int i = 0; i < 4; i++)
        #pragma unroll
        for (int j = 0; j < 4; j++) acc[i][j] = 0.f;

    for (int k0 = 0; k0 < K; k0 += 16) {
        float4 av = *(const float4*)&A[(size_t)(bm + a_row) * K + k0 + a_k4];
        float4 bv = make_float4(0.f, 0.f, 0.f, 0.f);
        if (bvalid)
            bv = *(const float4*)&W[(size_t)(k0 + b_k) * N + b_n4];

        As[a_k4 + 0][a_row] = av.x;
        As[a_k4 + 1][a_row] = av.y;
        As[a_k4 + 2][a_row] = av.z;
        As[a_k4 + 3][a_row] = av.w;
        *(float4*)&Bs[b_k][b_n4] = bv;
        __syncthreads();

        #pragma unroll
        for (int k = 0; k < 16; ++k) {
            float4 a4 = *(const float4*)&As[k][ty * 4];
            float4 b4 = *(const float4*)&Bs[k][tx * 4];
            float ar[4] = {a4.x, a4.y, a4.z, a4.w};
            float br[4] = {b4.x, b4.y, b4.z, b4.w};
            #pragma unroll
            for (int i = 0; i < 4; i++)
                #pragma unroll
                for (int j = 0; j < 4; j++)
                    acc[i][j] = fmaf(ar[i], br[j], acc[i][j]);
        }
        __syncthreads();
    }

    #pragma unroll
    for (int i = 0; i < 4; i++) {
        const int row = bm + ty * 4 + i;
        #pragma unroll
        for (int j = 0; j < 4; j++) {
            const int col = tx * 4 + j;
            if (col < N)
                C[(size_t)row * N + col] = acc[i][j] + bias[col];
        }
    }
}

// ---------------------------------------------------------------------------
// Deformable sampling v2: one WARP per (b, q); lane = (head = lane>>2,
// 8 channels via 2 x float4). Emits bf16 attn (one uint4 per lane).
// ---------------------------------------------------------------------------
__global__ void __launch_bounds__(256) sample_kernel(
    const float* __restrict__ refpts, __nv_bfloat16* __restrict__ out)
{
    const int gtid = blockIdx.x * blockDim.x + threadIdx.x;
    const int bq   = gtid >> 5;
    const int lane = gtid & 31;
    if (bq >= MROWS) return;

    const int h   = lane >> 2;
    const int sub = lane & 3;
    const int b   = bq / LQ;

    const float rx = refpts[(size_t)bq * 2 + 0] * (float)WIMG;
    const float ry = refpts[(size_t)bq * 2 + 1] * (float)HIMG;

    const float* awp = &g_aw[(size_t)bq * (NHEAD * NPNT) + h * NPNT];
    float a0 = awp[0], a1 = awp[1], a2 = awp[2], a3 = awp[3];
    float m  = fmaxf(fmaxf(a0, a1), fmaxf(a2, a3));
    float e0 = __expf(a0 - m), e1 = __expf(a1 - m);
    float e2 = __expf(a2 - m), e3 = __expf(a3 - m);
    float inv = 1.f / (e0 + e1 + e2 + e3);
    float aws[4] = {e0 * inv, e1 * inv, e2 * inv, e3 * inv};

    const float* offp  = &g_off[(size_t)bq * (NHEAD * NPNT * 2) + h * NPNT * 2];
    const float* vbase = &g_value[(size_t)b * LQ * CDIM + h * HDIM + sub * 8];

    float acc[8];
    #pragma unroll
    for (int i = 0; i < 8; i++) acc[i] = 0.f;

    #pragma unroll
    for (int p = 0; p < NPNT; p++) {
        float x = rx + offp[2 * p + 0] - 0.5f;
        float y = ry + offp[2 * p + 1] - 0.5f;
        float x0f = floorf(x), y0f = floorf(y);
        float lx = x - x0f, ly = y - y0f;
        int x0 = (int)x0f, y0 = (int)y0f;
        float w = aws[p];
        float wc[4] = {(1.f - lx) * (1.f - ly), lx * (1.f - ly),
                       (1.f - lx) * ly,         lx * ly};
        int xs[4] = {x0, x0 + 1, x0,     x0 + 1};
        int ys[4] = {y0, y0,     y0 + 1, y0 + 1};
        #pragma unroll
        for (int c = 0; c < 4; c++) {
            int xi = xs[c], yi = ys[c];
            if (xi >= 0 && xi < WIMG && yi >= 0 && yi < HIMG) {
                const float* vp = &vbase[(size_t)(yi * WIMG + xi) * CDIM];
                float4 v0 = *(const float4*)&vp[0];
                float4 v1 = *(const float4*)&vp[4];
                float ww = w * wc[c];
                acc[0] = fmaf(ww, v0.x, acc[0]);
                acc[1] = fmaf(ww, v0.y, acc[1]);
                acc[2] = fmaf(ww, v0.z, acc[2]);
                acc[3] = fmaf(ww, v0.w, acc[3]);
                acc[4] = fmaf(ww, v1.x, acc[4]);
                acc[5] = fmaf(ww, v1.y, acc[5]);
                acc[6] = fmaf(ww, v1.z, acc[6]);
                acc[7] = fmaf(ww, v1.w, acc[7]);
            }
        }
    }

    uint4 o;
    o.x = pack_bf16(acc[0], acc[1]);
    o.y = pack_bf16(acc[2], acc[3]);
    o.z = pack_bf16(acc[4], acc[5]);
    o.w = pack_bf16(acc[6], acc[7]);
    *(uint4*)&out[(size_t)bq * CDIM + h * HDIM + sub * 8] = o;
}

// ---------------------------------------------------------------------------
// LayerNorm over C=256: one warp per row. Optionally emits bf16 copy.
// ---------------------------------------------------------------------------
template<int WRITE_R>
__global__ void ln_kernel(const float* __restrict__ x,
                          const float* __restrict__ g,
                          const float* __restrict__ be,
                          float* __restrict__ y,
                          __nv_bfloat16* __restrict__ yr)
{
    const int gtid = blockIdx.x * blockDim.x + threadIdx.x;
    const int row  = gtid >> 5;
    const int lane = gtid & 31;
    if (row >= MROWS) return;

    const float* xr = x + (size_t)row * CDIM;
    float4 v0 = *(const float4*)&xr[lane * 4];
    float4 v1 = *(const float4*)&xr[128 + lane * 4];

    float s  = v0.x + v0.y + v0.z + v0.w + v1.x + v1.y + v1.z + v1.w;
    float sq = v0.x * v0.x + v0.y * v0.y + v0.z * v0.z + v0.w * v0.w
             + v1.x * v1.x + v1.y * v1.y + v1.z * v1.z + v1.w * v1.w;
    #pragma unroll
    for (int o = 16; o; o >>= 1) {
        s  += __shfl_xor_sync(0xffffffffu, s,  o);
        sq += __shfl_xor_sync(0xffffffffu, sq, o);
    }
    const float mean = s * (1.f / CDIM);
    const float var  = sq * (1.f / CDIM) - mean * mean;
    const float istd = rsqrtf(var + 1e-5f);

    float* yp = y + (size_t)row * CDIM;
    const int c0 = lane * 4;
    float4 o0, o1;
    o0.x = (v0.x - mean) * istd * g[c0 + 0] + be[c0 + 0];
    o0.y = (v0.y - mean) * istd * g[c0 + 1] + be[c0 + 1];
    o0.z = (v0.z - mean) * istd * g[c0 + 2] + be[c0 + 2];
    o0.w = (v0.w - mean) * istd * g[c0 + 3] + be[c0 + 3];
    o1.x = (v1.x - mean) * istd * g[128 + c0 + 0] + be[128 + c0 + 0];
    o1.y = (v1.y - mean) * istd * g[128 + c0 + 1] + be[128 + c0 + 1];
    o1.z = (v1.z - mean) * istd * g[128 + c0 + 2] + be[128 + c0 + 2];
    o1.w = (v1.w - mean) * istd * g[128 + c0 + 3] + be[128 + c0 + 3];
    *(float4*)&yp[c0]       = o0;
    *(float4*)&yp[128 + c0] = o1;
    if (WRITE_R) {
        __nv_bfloat16* rp = yr + (size_t)row * CDIM;
        uint2 r0, r1;
        r0.x = pack_bf16(o0.x, o0.y); r0.y = pack_bf16(o0.z, o0.w);
        r1.x = pack_bf16(o1.x, o1.y); r1.y = pack_bf16(o1.z, o1.w);
        *(uint2*)&rp[c0]       = r0;
        *(uint2*)&rp[128 + c0] = r1;
    }
}

// ---------------------------------------------------------------------------
// Launch sequence (graph-capturable: kernel launches only)
// ---------------------------------------------------------------------------
extern "C" void kernel_launch(void* const* d_in, const int* in_sizes, int n_in,
                              void* d_out, int out_size)
{
    const float* query = (const float*)d_in[0];
    const float* src   = (const float*)d_in[1];
    const float* refp  = (const float*)d_in[2];
    const float* W_off = (const float*)d_in[5];
    const float* b_off = (const float*)d_in[6];
    const float* W_aw  = (const float*)d_in[7];
    const float* b_aw  = (const float*)d_in[8];
    const float* W_val = (const float*)d_in[9];
    const float* b_val = (const float*)d_in[10];
    const float* W_out = (const float*)d_in[11];
    const float* b_out = (const float*)d_in[12];
    const float* g1    = (const float*)d_in[13];
    const float* be1   = (const float*)d_in[14];
    const float* W1    = (const float*)d_in[15];
    const float* b1    = (const float*)d_in[16];
    const float* W2    = (const float*)d_in[17];
    const float* b2    = (const float*)d_in[18];
    const float* g2    = (const float*)d_in[19];
    const float* be2   = (const float*)d_in[20];
    float* out = (float*)d_out;

    float *p_value, *p_off, *p_aw, *p_tmp, *p_q;
    __nv_bfloat16 *p_attn, *p_qr, *p_hidden, *p_srcr;
    __nv_bfloat16 *p_wvalT, *p_woutT, *p_w1T, *p_w2T;
    cudaGetSymbolAddress((void**)&p_value,  g_value);
    cudaGetSymbolAddress((void**)&p_off,    g_off);
    cudaGetSymbolAddress((void**)&p_aw,     g_aw);
    cudaGetSymbolAddress((void**)&p_attn,   g_attn);
    cudaGetSymbolAddress((void**)&p_tmp,    g_tmp);
    cudaGetSymbolAddress((void**)&p_q,      g_q);
    cudaGetSymbolAddress((void**)&p_qr,     g_qr);
    cudaGetSymbolAddress((void**)&p_hidden, g_hidden);
    cudaGetSymbolAddress((void**)&p_srcr,   g_srcr);
    cudaGetSymbolAddress((void**)&p_wvalT,  g_wvalT);
    cudaGetSymbolAddress((void**)&p_woutT,  g_woutT);
    cudaGetSymbolAddress((void**)&p_w1T,    g_w1T);
    cudaGetSymbolAddress((void**)&p_w2T,    g_w2T);

    const int MB128 = MROWS / 128;  // 625
    const int MB64  = MROWS / 64;   // 1250

    // 0) prep: convert src to bf16; transpose weights to bf16 [N,K]
    {
        size_t n4 = (size_t)MROWS * CDIM / 4;
        cvt_bf16_kernel<<<(unsigned)((n4 + 255) / 256), 256>>>(src, p_srcr, n4);
        dim3 blk(32, 8);
        transpose_bf16_kernel<<<dim3(CDIM / 32, CDIM / 32), blk>>>(W_val, p_wvalT, CDIM, CDIM);
        transpose_bf16_kernel<<<dim3(CDIM / 32, CDIM / 32), blk>>>(W_out, p_woutT, CDIM, CDIM);
        transpose_bf16_kernel<<<dim3(DFFN / 32, CDIM / 32), blk>>>(W1, p_w1T, CDIM, DFFN);
        transpose_bf16_kernel<<<dim3(CDIM / 32, DFFN / 32), blk>>>(W2, p_w2T, DFFN, CDIM);
    }

    // 1) value = srcr @ W_val + b_val  (f32 out)           [80000 x 256 x 256]
    gemm_bf16<0, 0><<<dim3(CDIM / 128, MB128), 256>>>(p_srcr, p_wvalT, b_val, nullptr, p_value, CDIM, CDIM);
    // 2) off logits (fp32 exact — feeds floor())           [80000 x 64 x 256]
    gemm_small_kernel<<<dim3(1, MB64), 256>>>(query, W_off, b_off, p_off, 64, CDIM);
    // 3) aw logits (fp32 exact)                            [80000 x 32 x 256]
    gemm_small_kernel<<<dim3(1, MB64), 256>>>(query, W_aw, b_aw, p_aw, 32, CDIM);
    // 4) softmax + bilinear sampling -> attn (bf16)
    sample_kernel<<<(MROWS * 32 + 255) / 256, 256>>>(refp, p_attn);
    // 5) tmp = attn @ W_out + b_out + query (f32 out)      [80000 x 256 x 256]
    gemm_bf16<2, 0><<<dim3(CDIM / 128, MB128), 256>>>(p_attn, p_woutT, b_out, query, p_tmp, CDIM, CDIM);
    // 6) q = LN1(tmp); qr = bf16(q)
    ln_kernel<1><<<(MROWS * 32 + 255) / 256, 256>>>(p_tmp, g1, be1, p_q, p_qr);
    // 7) hidden = bf16(relu(qr @ W1 + b1))                 [80000 x 1024 x 256]
    gemm_bf16<1, 1><<<dim3(DFFN / 128, MB128), 256>>>(p_qr, p_w1T, b1, nullptr, p_hidden, DFFN, CDIM);
    // 8) tmp = hidden @ W2 + b2 + q (f32 out)              [80000 x 256 x 1024]
    gemm_bf16<2, 0><<<dim3(CDIM / 128, MB128), 256>>>(p_hidden, p_w2T, b2, p_q, p_tmp, CDIM, DFFN);
    // 9) out = LN2(tmp)
    ln_kernel<0><<<(MROWS * 32 + 255) / 256, 256>>>(p_tmp, g2, be2, out, nullptr);
}